// round 2
// baseline (speedup 1.0000x reference)
#include <cuda_runtime.h>
#include <cstdint>

// Problem constants
#define BB 48
#define LL 128
#define DD 1024
#define HH 150      // ffnn out
#define HP 151      // +bias col
#define OO 9
#define LDX 160     // padded feature stride (cols 151..159 zero)

#define N_CELLS (LL*LL)              // 16384
#define SCORE_ELEMS (BB*LL*LL*OO)    // 7077888
#define RESULT_ELEMS (BB*LL*LL)      // 786432

// ---------------- static device scratch (no runtime allocation allowed) ------
__device__ float Xg[(size_t)BB*LL*LDX];               // [6144][160], col150=1, 151..159=0
__device__ float Yg[(size_t)BB*LL*LDX];
__device__ float Tg[(size_t)BB*OO*LL*LDX];            // [(b*9+o)][128][160]
__device__ float Sg[(size_t)SCORE_ELEMS];             // fallback score buffer

// ---------------- f32x2 helpers ---------------------------------------------
__device__ __forceinline__ void fma2(unsigned long long& d, unsigned long long a,
                                     unsigned long long b) {
    asm("fma.rn.f32x2 %0, %1, %2, %0;" : "+l"(d) : "l"(a), "l"(b));
}
__device__ __forceinline__ unsigned long long pack2(float x) {
    unsigned long long r;
    asm("mov.b64 %0, {%1, %1};" : "=l"(r) : "f"(x));
    return r;
}
__device__ __forceinline__ float2 unpack2(unsigned long long v) {
    float2 f;
    asm("mov.b64 {%0, %1}, %2;" : "=f"(f.x), "=f"(f.y) : "l"(v));
    return f;
}

// 8-row x 8-col (4 f32x2) micro step
__device__ __forceinline__ void micro_step(const float* __restrict__ aRow,
                                           const float* __restrict__ bRow,
                                           unsigned long long acc[8][4]) {
    float4 a0 = *(const float4*)(aRow);
    float4 a1 = *(const float4*)(aRow + 4);
    ulonglong2 q0 = *(const ulonglong2*)(bRow);
    ulonglong2 q1 = *(const ulonglong2*)(bRow + 4);
    unsigned long long bb[4] = {q0.x, q0.y, q1.x, q1.y};
    float av[8] = {a0.x, a0.y, a0.z, a0.w, a1.x, a1.y, a1.z, a1.w};
#pragma unroll
    for (int r = 0; r < 8; r++) {
        unsigned long long ap = pack2(av[r]);
#pragma unroll
        for (int p = 0; p < 4; p++) fma2(acc[r][p], ap, bb[p]);
    }
}

// ============================================================================
// Kernel 1: projections.  X/Y[r][c] = bert[r]·w[c] + bias[c]; col150=1; pad=0
// grid (48, 2): blockIdx.x = 128-row tile, blockIdx.y = 0(start/X) 1(end/Y)
// block 320 = 16(ty, rows) x 20(tx, col-octets)
// ============================================================================
__global__ __launch_bounds__(320) void proj_kernel(
    const float* __restrict__ bert,
    const float* __restrict__ wS, const float* __restrict__ bS,
    const float* __restrict__ wE, const float* __restrict__ bE) {
    const int z = blockIdx.y;
    const float* w    = z ? wE : wS;
    const float* bias = z ? bE : bS;
    float* outp       = z ? Yg : Xg;
    const int mBase = blockIdx.x * 128;

    __shared__ alignas(16) float As[16][132];
    __shared__ alignas(16) float Bs[16][164];

    const int t = threadIdx.x;
    const int tx = t % 20, ty = t / 20;

    unsigned long long acc[8][4];
#pragma unroll
    for (int r = 0; r < 8; r++)
#pragma unroll
        for (int p = 0; p < 4; p++) acc[r][p] = 0ull;

    for (int k0 = 0; k0 < DD; k0 += 16) {
        for (int e = t; e < 128 * 16; e += 320) {
            int row = e >> 4, kk = e & 15;
            As[kk][row] = bert[(size_t)(mBase + row) * DD + k0 + kk];
        }
        for (int e = t; e < 160 * 16; e += 320) {
            int c = e >> 4, kk = e & 15;
            Bs[kk][c] = (c < HH) ? w[(size_t)c * DD + k0 + kk] : 0.f;
        }
        __syncthreads();
#pragma unroll
        for (int kk = 0; kk < 16; kk++)
            micro_step(&As[kk][ty * 8], &Bs[kk][tx * 8], acc);
        __syncthreads();
    }

#pragma unroll
    for (int r = 0; r < 8; r++) {
        int row = mBase + ty * 8 + r;
        float* orow = &outp[(size_t)row * LDX];
#pragma unroll
        for (int p = 0; p < 4; p++) {
            float2 v = unpack2(acc[r][p]);
            int c0 = tx * 8 + 2 * p;
            float o0 = (c0 < HH) ? v.x + bias[c0] : (c0 == HH ? 1.f : 0.f);
            int c1 = c0 + 1;
            float o1 = (c1 < HH) ? v.y + bias[c1] : (c1 == HH ? 1.f : 0.f);
            orow[c0] = o0;
            orow[c1] = o1;
        }
    }
}

// ============================================================================
// Kernel 2: T[(b,o)][x][j] = sum_i X[b][x][i] * W[o][i][j]    (K=160, pads 0)
// grid 432 (= b*9+o), block 320
// ============================================================================
__global__ __launch_bounds__(320) void biaff_left(const float* __restrict__ Wb) {
    const int blk = blockIdx.x;
    const int b = blk / OO, o = blk % OO;
    const float* Xb = &Xg[(size_t)b * LL * LDX];
    const float* Wo = Wb + (size_t)o * HP * HP;
    float* Tp = &Tg[(size_t)blk * LL * LDX];

    __shared__ alignas(16) float As[16][132];
    __shared__ alignas(16) float Bs[16][164];

    const int t = threadIdx.x;
    const int tx = t % 20, ty = t / 20;

    unsigned long long acc[8][4];
#pragma unroll
    for (int r = 0; r < 8; r++)
#pragma unroll
        for (int p = 0; p < 4; p++) acc[r][p] = 0ull;

    for (int k0 = 0; k0 < LDX; k0 += 16) {
        for (int e = t; e < 128 * 16; e += 320) {
            int row = e >> 4, kk = e & 15;
            As[kk][row] = Xb[(size_t)row * LDX + k0 + kk];
        }
        for (int e = t; e < 160 * 16; e += 320) {
            int kk = e / 160, j = e % 160;
            int i = k0 + kk;
            Bs[kk][j] = (i < HP && j < HP) ? Wo[(size_t)i * HP + j] : 0.f;
        }
        __syncthreads();
#pragma unroll
        for (int kk = 0; kk < 16; kk++)
            micro_step(&As[kk][ty * 8], &Bs[kk][tx * 8], acc);
        __syncthreads();
    }

#pragma unroll
    for (int r = 0; r < 8; r++) {
        float* orow = &Tp[(size_t)(ty * 8 + r) * LDX];
#pragma unroll
        for (int p = 0; p < 4; p++) {
            float2 v = unpack2(acc[r][p]);
            int c0 = tx * 8 + 2 * p;
            orow[c0] = v.x;
            orow[c0 + 1] = v.y;
        }
    }
}

// ============================================================================
// Kernel 3: score[b][x][y][o] = sum_j T[(b,o)][x][j] * Y[b][y][j]
// grid 432, block 256 = 16x16
// ============================================================================
__global__ __launch_bounds__(256) void biaff_right(float* __restrict__ outp) {
    const int blk = blockIdx.x;
    const int b = blk / OO, o = blk % OO;
    const float* Tp = &Tg[(size_t)blk * LL * LDX];
    const float* Yb = &Yg[(size_t)b * LL * LDX];

    __shared__ alignas(16) float As[16][132];
    __shared__ alignas(16) float Bs[16][132];

    const int t = threadIdx.x;
    const int tx = t % 16, ty = t / 16;

    unsigned long long acc[8][4];
#pragma unroll
    for (int r = 0; r < 8; r++)
#pragma unroll
        for (int p = 0; p < 4; p++) acc[r][p] = 0ull;

    for (int k0 = 0; k0 < LDX; k0 += 16) {
        for (int e = t; e < 128 * 16; e += 256) {
            int row = e >> 4, kk = e & 15;
            As[kk][row] = Tp[(size_t)row * LDX + k0 + kk];
        }
        for (int e = t; e < 128 * 16; e += 256) {
            int row = e >> 4, kk = e & 15;
            Bs[kk][row] = Yb[(size_t)row * LDX + k0 + kk];
        }
        __syncthreads();
#pragma unroll
        for (int kk = 0; kk < 16; kk++)
            micro_step(&As[kk][ty * 8], &Bs[kk][tx * 8], acc);
        __syncthreads();
    }

#pragma unroll
    for (int r = 0; r < 8; r++) {
        int x = ty * 8 + r;
        size_t base = ((size_t)(b * LL + x) * LL) * OO + o;
#pragma unroll
        for (int p = 0; p < 4; p++) {
            float2 v = unpack2(acc[r][p]);
            int y0 = tx * 8 + 2 * p;
            outp[base + (size_t)y0 * OO] = v.x;
            outp[base + (size_t)(y0 + 1) * OO] = v.y;
        }
    }
}

// ============================================================================
// Kernel 4: per-sentence greedy decode.
// grid 48, block 1024, dyn smem = 16384*8 (keys) + 16384 (argmax bytes)
// ============================================================================
__device__ __forceinline__ unsigned long long rmask64(int lo, int hi) {
    unsigned long long m = (hi >= 63) ? ~0ull : ((1ull << (hi + 1)) - 1ull);
    return m & (~0ull << lo);
}

__global__ __launch_bounds__(1024) void decode_kernel(
    const float* __restrict__ score,
    const int* __restrict__ tagseq,
    float* __restrict__ resOut) {
    const int b = blockIdx.x;
    const int tid = threadIdx.x;

    extern __shared__ unsigned long long smdyn[];
    unsigned long long* keys = smdyn;                       // 16384 u64
    unsigned char* ansS = (unsigned char*)(smdyn + N_CELLS); // 16384 u8

    const float* sB = score + (size_t)b * N_CELLS * OO;
    const int* mB = tagseq + (size_t)b * N_CELLS;
    float* rB = resOut + (size_t)b * N_CELLS;

    // Phase 1: argmax over O, validity, packed sort keys, result init
    for (int idx = tid; idx < N_CELLS; idx += blockDim.x) {
        const float* sp = sB + (size_t)idx * OO;
        float best = sp[0];
        int bo = 0;
#pragma unroll
        for (int o = 1; o < OO; o++) {
            float v = sp[o];
            if (v > best) { best = v; bo = o; }
        }
        ansS[idx] = (unsigned char)bo;
        bool valid = (bo != 1) && (mB[idx] > 0);
        unsigned u = __float_as_uint(best);
        u ^= (u & 0x80000000u) ? 0xFFFFFFFFu : 0x80000000u;  // ascending-orderable
        unsigned ud = ~u;                                    // descending-orderable
        if (!valid) ud = 0xFFFFFFFFu;
        keys[idx] = ((unsigned long long)ud << 32) | (unsigned)idx;
        rB[idx] = 1.0f;  // NON_ENTITY
    }
    __syncthreads();

    // Phase 2: bitonic sort ascending (desc score, ties row-major)
    for (unsigned k = 2; k <= (unsigned)N_CELLS; k <<= 1) {
        for (unsigned j = k >> 1; j > 0; j >>= 1) {
            for (unsigned e = tid; e < (unsigned)N_CELLS; e += blockDim.x) {
                unsigned ixj = e ^ j;
                if (ixj > e) {
                    unsigned long long a = keys[e], c = keys[ixj];
                    bool up = (e & k) == 0;
                    if ((a > c) == up) { keys[e] = c; keys[ixj] = a; }
                }
            }
            __syncthreads();
        }
    }

    // Phase 3: warp 0 speculative-window greedy scan
    if (tid < 32) {
        const unsigned FULL = 0xFFFFFFFFu;
        unsigned long long st0 = 0, st1 = 0, cv0 = 0, cv1 = 0;
        int t = 0;
        while (t < N_CELLS) {
            int my = t + tid;
            unsigned long long kk = (my < N_CELLS) ? keys[my]
                                                   : 0xFFFFFFFF00000000ull;
            unsigned ud = (unsigned)(kk >> 32);
            bool isval = (ud != 0xFFFFFFFFu);
            int idx = (int)(unsigned)kk;
            int i = idx >> 7, j = idx & 127;

            bool upper = (j >= i);
            unsigned long long sp0 = 0, sp1 = 0;
            if (upper) {
                if (i <= 63) sp0 = rmask64(i, j < 63 ? j : 63);
                if (j >= 64) sp1 = rmask64(i > 64 ? i - 64 : 0, j - 64);
            }
            bool stbit = (i < 64) ? ((st0 >> i) & 1ull) : ((st1 >> (i - 64)) & 1ull);
            bool cvbit = (i < 64) ? ((cv0 >> i) & 1ull) : ((cv1 >> (i - 64)) & 1ull);
            bool conflict = (((st0 & sp0) | (st1 & sp1)) != 0ull) || cvbit;
            bool acc = isval && !conflict;
            bool schg = acc && (upper || !stbit);

            unsigned bInv = __ballot_sync(FULL, !isval);
            int fI = bInv ? (__ffs(bInv) - 1) : 32;
            unsigned bS = __ballot_sync(FULL, schg);
            if (fI < 32) bS &= (fI ? ((1u << fI) - 1u) : 0u);
            int fS = bS ? (__ffs(bS) - 1) : 32;
            int lim = fS < fI ? fS : fI;

            // finalized plain accepts (no state change) before first changer
            if (acc && (int)tid < lim) rB[idx] = (float)ansS[idx];

            if (fS < fI && fS < 32) {
                if ((int)tid == fS) {
                    rB[idx] = (float)ansS[idx];
                    if (i < 64) st0 |= (1ull << i); else st1 |= (1ull << (i - 64));
                    if (upper) { cv0 |= sp0; cv1 |= sp1; }
                }
                st0 = __shfl_sync(FULL, st0, fS);
                st1 = __shfl_sync(FULL, st1, fS);
                cv0 = __shfl_sync(FULL, cv0, fS);
                cv1 = __shfl_sync(FULL, cv1, fS);
                t += fS + 1;
            } else if (fI < 32) {
                break;  // sorted invalid tail reached
            } else {
                t += 32;
            }
        }
    }
}

// ============================================================================
extern "C" void kernel_launch(void* const* d_in, const int* in_sizes, int n_in,
                              void* d_out, int out_size) {
    (void)in_sizes; (void)n_in;
    const float* bert = (const float*)d_in[0];
    const int*   tagseq = (const int*)d_in[1];
    const float* wS = (const float*)d_in[2];
    const float* bS = (const float*)d_in[3];
    const float* wE = (const float*)d_in[4];
    const float* bE = (const float*)d_in[5];
    const float* Wb = (const float*)d_in[6];
    float* out = (float*)d_out;

    bool scoreInOut = (out_size >= SCORE_ELEMS);
    float* scorePtr = out;
    if (!scoreInOut) {
        void* p = nullptr;
        cudaGetSymbolAddress(&p, Sg);
        scorePtr = (float*)p;
    }

    proj_kernel<<<dim3(48, 2), 320>>>(bert, wS, bS, wE, bE);
    biaff_left<<<432, 320>>>(Wb);
    biaff_right<<<432, 256>>>(scorePtr);

    float* resPtr = nullptr;
    if (out_size >= SCORE_ELEMS + RESULT_ELEMS) resPtr = out + SCORE_ELEMS;
    else if (!scoreInOut && out_size >= RESULT_ELEMS) resPtr = out;

    if (resPtr) {
        const int dynsmem = N_CELLS * 8 + N_CELLS;  // keys + ans bytes
        cudaFuncSetAttribute(decode_kernel,
                             cudaFuncAttributeMaxDynamicSharedMemorySize, dynsmem);
        decode_kernel<<<48, 1024, dynsmem>>>(scorePtr, tagseq, resPtr);
    }
}

// round 3
// speedup vs baseline: 1.1850x; 1.1850x over previous
#include <cuda_runtime.h>
#include <cstdint>

// Problem constants
#define BB 48
#define LL 128
#define DD 1024
#define HH 150      // ffnn out
#define HP 151      // +bias col
#define OO 9
#define LDX 160     // padded feature stride (cols 151..159 zero)

#define N_CELLS (LL*LL)              // 16384
#define SCORE_ELEMS (BB*LL*LL*OO)    // 7077888
#define RESULT_ELEMS (BB*LL*LL)      // 786432

#define FULLMASK 0xFFFFFFFFu

// ---------------- static device scratch (no runtime allocation allowed) ------
__device__ float Xg[(size_t)BB*LL*LDX];               // [6144][160], col150=1, 151..159=0
__device__ float Yg[(size_t)BB*LL*LDX];
__device__ float Tg[(size_t)BB*OO*LL*LDX];            // [(b*9+o)][128][160]
__device__ float Sg[(size_t)SCORE_ELEMS];             // fallback score buffer
__device__ unsigned char AnsG[(size_t)BB*N_CELLS];    // per-cell argmax label

// ---------------- f32x2 helpers ---------------------------------------------
__device__ __forceinline__ void fma2(unsigned long long& d, unsigned long long a,
                                     unsigned long long b) {
    asm("fma.rn.f32x2 %0, %1, %2, %0;" : "+l"(d) : "l"(a), "l"(b));
}
__device__ __forceinline__ unsigned long long pack2(float x) {
    unsigned long long r;
    asm("mov.b64 %0, {%1, %1};" : "=l"(r) : "f"(x));
    return r;
}
__device__ __forceinline__ float2 unpack2(unsigned long long v) {
    float2 f;
    asm("mov.b64 {%0, %1}, %2;" : "=f"(f.x), "=f"(f.y) : "l"(v));
    return f;
}

// 8-row x 8-col (4 f32x2) micro step
__device__ __forceinline__ void micro_step8(const float* __restrict__ aRow,
                                            const float* __restrict__ bRow,
                                            unsigned long long acc[8][4]) {
    float4 a0 = *(const float4*)(aRow);
    float4 a1 = *(const float4*)(aRow + 4);
    ulonglong2 q0 = *(const ulonglong2*)(bRow);
    ulonglong2 q1 = *(const ulonglong2*)(bRow + 4);
    unsigned long long bb[4] = {q0.x, q0.y, q1.x, q1.y};
    float av[8] = {a0.x, a0.y, a0.z, a0.w, a1.x, a1.y, a1.z, a1.w};
#pragma unroll
    for (int r = 0; r < 8; r++) {
        unsigned long long ap = pack2(av[r]);
#pragma unroll
        for (int p = 0; p < 4; p++) fma2(acc[r][p], ap, bb[p]);
    }
}

// 4-row x 8-col micro step
__device__ __forceinline__ void micro_step4(const float* __restrict__ aRow,
                                            const float* __restrict__ bRow,
                                            unsigned long long acc[4][4]) {
    float4 a0 = *(const float4*)(aRow);
    ulonglong2 q0 = *(const ulonglong2*)(bRow);
    ulonglong2 q1 = *(const ulonglong2*)(bRow + 4);
    unsigned long long bb[4] = {q0.x, q0.y, q1.x, q1.y};
    float av[4] = {a0.x, a0.y, a0.z, a0.w};
#pragma unroll
    for (int r = 0; r < 4; r++) {
        unsigned long long ap = pack2(av[r]);
#pragma unroll
        for (int p = 0; p < 4; p++) fma2(acc[r][p], ap, bb[p]);
    }
}

// ============================================================================
// Kernel 1: projections.  X/Y[r][c] = bert[r]·w[c] + bias[c]; col150=1; pad=0
// grid (96, 2): blockIdx.x = 64-row tile, blockIdx.y = 0(start/X) 1(end/Y)
// block 320 = 16(ty, 4-row groups) x 20(tx, col-octets)
// ============================================================================
__global__ __launch_bounds__(320) void proj_kernel(
    const float* __restrict__ bert,
    const float* __restrict__ wS, const float* __restrict__ bS,
    const float* __restrict__ wE, const float* __restrict__ bE) {
    const int z = blockIdx.y;
    const float* w    = z ? wE : wS;
    const float* bias = z ? bE : bS;
    float* outp       = z ? Yg : Xg;
    const int mBase = blockIdx.x * 64;

    __shared__ alignas(16) float As[16][68];
    __shared__ alignas(16) float Bs[16][164];

    const int t = threadIdx.x;
    const int tx = t % 20, ty = t / 20;

    unsigned long long acc[4][4];
#pragma unroll
    for (int r = 0; r < 4; r++)
#pragma unroll
        for (int p = 0; p < 4; p++) acc[r][p] = 0ull;

    for (int k0 = 0; k0 < DD; k0 += 16) {
        for (int e = t; e < 64 * 16; e += 320) {
            int row = e >> 4, kk = e & 15;
            As[kk][row] = bert[(size_t)(mBase + row) * DD + k0 + kk];
        }
        for (int e = t; e < 160 * 16; e += 320) {
            int c = e >> 4, kk = e & 15;
            Bs[kk][c] = (c < HH) ? w[(size_t)c * DD + k0 + kk] : 0.f;
        }
        __syncthreads();
#pragma unroll
        for (int kk = 0; kk < 16; kk++)
            micro_step4(&As[kk][ty * 4], &Bs[kk][tx * 8], acc);
        __syncthreads();
    }

#pragma unroll
    for (int r = 0; r < 4; r++) {
        int row = mBase + ty * 4 + r;
        float* orow = &outp[(size_t)row * LDX];
#pragma unroll
        for (int p = 0; p < 4; p++) {
            float2 v = unpack2(acc[r][p]);
            int c0 = tx * 8 + 2 * p;
            float o0 = (c0 < HH) ? v.x + bias[c0] : (c0 == HH ? 1.f : 0.f);
            int c1 = c0 + 1;
            float o1 = (c1 < HH) ? v.y + bias[c1] : (c1 == HH ? 1.f : 0.f);
            orow[c0] = o0;
            orow[c1] = o1;
        }
    }
}

// ============================================================================
// Kernel 2: T[(b,o)][x][j] = sum_i X[b][x][i] * W[o][i][j]    (K=160, pads 0)
// grid 432 (= b*9+o), block 320
// ============================================================================
__global__ __launch_bounds__(320) void biaff_left(const float* __restrict__ Wb) {
    const int blk = blockIdx.x;
    const int b = blk / OO, o = blk % OO;
    const float* Xb = &Xg[(size_t)b * LL * LDX];
    const float* Wo = Wb + (size_t)o * HP * HP;
    float* Tp = &Tg[(size_t)blk * LL * LDX];

    __shared__ alignas(16) float As[16][132];
    __shared__ alignas(16) float Bs[16][164];

    const int t = threadIdx.x;
    const int tx = t % 20, ty = t / 20;

    unsigned long long acc[8][4];
#pragma unroll
    for (int r = 0; r < 8; r++)
#pragma unroll
        for (int p = 0; p < 4; p++) acc[r][p] = 0ull;

    for (int k0 = 0; k0 < LDX; k0 += 16) {
        for (int e = t; e < 128 * 16; e += 320) {
            int row = e >> 4, kk = e & 15;
            As[kk][row] = Xb[(size_t)row * LDX + k0 + kk];
        }
        for (int e = t; e < 160 * 16; e += 320) {
            int kk = e / 160, j = e % 160;
            int i = k0 + kk;
            Bs[kk][j] = (i < HP && j < HP) ? Wo[(size_t)i * HP + j] : 0.f;
        }
        __syncthreads();
#pragma unroll
        for (int kk = 0; kk < 16; kk++)
            micro_step8(&As[kk][ty * 8], &Bs[kk][tx * 8], acc);
        __syncthreads();
    }

#pragma unroll
    for (int r = 0; r < 8; r++) {
        float* orow = &Tp[(size_t)(ty * 8 + r) * LDX];
#pragma unroll
        for (int p = 0; p < 4; p++) {
            float2 v = unpack2(acc[r][p]);
            int c0 = tx * 8 + 2 * p;
            orow[c0] = v.x;
            orow[c0 + 1] = v.y;
        }
    }
}

// ============================================================================
// Kernel 3: score[b][x][y][o] = sum_j T[(b,o)][x][j] * Y[b][y][j]
// grid 432, block 256 = 16x16
// ============================================================================
__global__ __launch_bounds__(256) void biaff_right(float* __restrict__ outp) {
    const int blk = blockIdx.x;
    const int b = blk / OO, o = blk % OO;
    const float* Tp = &Tg[(size_t)blk * LL * LDX];
    const float* Yb = &Yg[(size_t)b * LL * LDX];

    __shared__ alignas(16) float As[16][132];
    __shared__ alignas(16) float Bs[16][132];

    const int t = threadIdx.x;
    const int tx = t % 16, ty = t / 16;

    unsigned long long acc[8][4];
#pragma unroll
    for (int r = 0; r < 8; r++)
#pragma unroll
        for (int p = 0; p < 4; p++) acc[r][p] = 0ull;

    for (int k0 = 0; k0 < LDX; k0 += 16) {
        for (int e = t; e < 128 * 16; e += 256) {
            int row = e >> 4, kk = e & 15;
            As[kk][row] = Tp[(size_t)row * LDX + k0 + kk];
        }
        for (int e = t; e < 128 * 16; e += 256) {
            int row = e >> 4, kk = e & 15;
            Bs[kk][row] = Yb[(size_t)row * LDX + k0 + kk];
        }
        __syncthreads();
#pragma unroll
        for (int kk = 0; kk < 16; kk++)
            micro_step8(&As[kk][ty * 8], &Bs[kk][tx * 8], acc);
        __syncthreads();
    }

#pragma unroll
    for (int r = 0; r < 8; r++) {
        int x = ty * 8 + r;
        size_t base = ((size_t)(b * LL + x) * LL) * OO + o;
#pragma unroll
        for (int p = 0; p < 4; p++) {
            float2 v = unpack2(acc[r][p]);
            int y0 = tx * 8 + 2 * p;
            outp[base + (size_t)y0 * OO] = v.x;
            outp[base + (size_t)(y0 + 1) * OO] = v.y;
        }
    }
}

// ============================================================================
// Kernel 4: per-sentence greedy decode with LSD radix sort.
// grid 48, block 1024.
// Dynamic smem layout (bytes):
//   [0,      65536)  keyA  u32[16384]
//   [65536, 131072)  keyB  u32[16384]
//   [131072,163840)  payA  u16[16384]
//   [163840,196608)  payB  u16[16384]
//   [196608,212992)  hist  u16[8192]   (digit-major: h = d*32 + warp)
//   [212992,213120)  scanW u32[32]
// ============================================================================
#define DEC_SMEM 213120

__device__ __forceinline__ unsigned long long rmask64(int lo, int hi) {
    unsigned long long m = (hi >= 63) ? ~0ull : ((1ull << (hi + 1)) - 1ull);
    return m & (~0ull << lo);
}

__global__ __launch_bounds__(1024) void decode_kernel(
    const float* __restrict__ score,
    const int* __restrict__ tagseq,
    float* __restrict__ resOut) {
    const int b = blockIdx.x;
    const int tid = threadIdx.x;
    const int wrp = tid >> 5, lane = tid & 31;
    const unsigned laneLT = (lane == 0) ? 0u : ((1u << lane) - 1u);

    extern __shared__ char smdyn[];
    unsigned* keyA = (unsigned*)(smdyn);
    unsigned* keyB = (unsigned*)(smdyn + 65536);
    unsigned short* payA = (unsigned short*)(smdyn + 131072);
    unsigned short* payB = (unsigned short*)(smdyn + 163840);
    unsigned short* hist = (unsigned short*)(smdyn + 196608);
    unsigned* scanW = (unsigned*)(smdyn + 212992);

    const float* sB = score + (size_t)b * N_CELLS * OO;
    const int* mB = tagseq + (size_t)b * N_CELLS;
    float* rB = resOut + (size_t)b * N_CELLS;
    unsigned char* aB = AnsG + (size_t)b * N_CELLS;

    // ---- Phase 1: argmax over O, validity, sort keys, result init ----------
    for (int idx = tid; idx < N_CELLS; idx += 1024) {
        const float* sp = sB + (size_t)idx * OO;
        float best = sp[0];
        int bo = 0;
#pragma unroll
        for (int o = 1; o < OO; o++) {
            float v = sp[o];
            if (v > best) { best = v; bo = o; }
        }
        aB[idx] = (unsigned char)bo;
        bool valid = (bo != 1) && (mB[idx] > 0);
        unsigned u = __float_as_uint(best);
        u ^= (u & 0x80000000u) ? 0xFFFFFFFFu : 0x80000000u;  // ascending-orderable
        unsigned ud = ~u;                                    // descending-orderable
        if (!valid) ud = 0xFFFFFFFFu;
        keyA[idx] = ud;
        payA[idx] = (unsigned short)idx;
        rB[idx] = 1.0f;  // NON_ENTITY
    }
    __syncthreads();

    // ---- Phase 2: stable LSD radix sort, 4x8-bit passes --------------------
    const int chunk = wrp * 512;  // this warp's 512 consecutive items
#pragma unroll
    for (int pass = 0; pass < 4; pass++) {
        const int shift = pass * 8;
        unsigned* srcK = (pass & 1) ? keyB : keyA;
        unsigned* dstK = (pass & 1) ? keyA : keyB;
        unsigned short* srcP = (pass & 1) ? payB : payA;
        unsigned short* dstP = (pass & 1) ? payA : payB;

        // zero histogram
        for (int h = tid; h < 8192; h += 1024) hist[h] = 0;
        __syncthreads();

        // count: 16 rounds, item order = chunk + r*32 + lane (stable)
#pragma unroll 4
        for (int r = 0; r < 16; r++) {
            unsigned k = srcK[chunk + r * 32 + lane];
            unsigned d = (k >> shift) & 255u;
            unsigned m = __match_any_sync(FULLMASK, d);
            if ((m & laneLT) == 0)  // leader of digit group
                hist[d * 32 + wrp] = (unsigned short)(hist[d * 32 + wrp] + __popc(m));
        }
        __syncthreads();

        // exclusive scan over hist[0..8191] (digit-major, warp-minor)
        {
            int h0 = tid * 8;
            unsigned short loc[8];
            unsigned s = 0;
#pragma unroll
            for (int q = 0; q < 8; q++) { loc[q] = hist[h0 + q]; s += loc[q]; }
            unsigned v = s;
#pragma unroll
            for (int off = 1; off < 32; off <<= 1) {
                unsigned n = __shfl_up_sync(FULLMASK, v, off);
                if (lane >= off) v += n;
            }
            if (lane == 31) scanW[wrp] = v;
            __syncthreads();
            if (tid < 32) {
                unsigned wv = scanW[tid];
                unsigned iv = wv;
#pragma unroll
                for (int off = 1; off < 32; off <<= 1) {
                    unsigned n = __shfl_up_sync(FULLMASK, iv, off);
                    if (tid >= off) iv += n;
                }
                scanW[tid] = iv - wv;  // exclusive
            }
            __syncthreads();
            unsigned run = scanW[wrp] + (v - s);  // thread-exclusive global prefix
#pragma unroll
            for (int q = 0; q < 8; q++) {
                unsigned c = loc[q];
                hist[h0 + q] = (unsigned short)run;
                run += c;
            }
        }
        __syncthreads();

        // scatter: same 16 rounds, running per-warp digit counters in hist
#pragma unroll 4
        for (int r = 0; r < 16; r++) {
            int idx = chunk + r * 32 + lane;
            unsigned k = srcK[idx];
            unsigned short p = srcP[idx];
            unsigned d = (k >> shift) & 255u;
            unsigned m = __match_any_sync(FULLMASK, d);
            int rank = __popc(m & laneLT);
            int leaderLane = __ffs(m) - 1;
            unsigned baseOff = 0;
            if (lane == leaderLane) {
                baseOff = hist[d * 32 + wrp];
                hist[d * 32 + wrp] = (unsigned short)(baseOff + __popc(m));
            }
            baseOff = __shfl_sync(FULLMASK, baseOff, leaderLane);
            dstK[baseOff + rank] = k;
            dstP[baseOff + rank] = p;
        }
        __syncthreads();
    }
    // sorted result is in keyA / payA (4 passes)

    // ---- Phase 3: warp 0 speculative-window greedy scan --------------------
    if (tid < 32) {
        unsigned long long st0 = 0, st1 = 0, cv0 = 0, cv1 = 0;
        int t = 0;
        while (t < N_CELLS) {
            int my = t + lane;
            unsigned ud = (my < N_CELLS) ? keyA[my] : 0xFFFFFFFFu;
            int idx = (my < N_CELLS) ? (int)payA[my] : 0;
            bool isval = (ud != 0xFFFFFFFFu);
            int i = idx >> 7, j = idx & 127;
            int av = (int)aB[idx];  // early L2 load, used only on accept

            bool upper = (j >= i);
            unsigned long long sp0 = 0, sp1 = 0;
            if (upper) {
                if (i <= 63) sp0 = rmask64(i, j < 63 ? j : 63);
                if (j >= 64) sp1 = rmask64(i > 64 ? i - 64 : 0, j - 64);
            }
            bool stbit = (i < 64) ? ((st0 >> i) & 1ull) : ((st1 >> (i - 64)) & 1ull);
            bool cvbit = (i < 64) ? ((cv0 >> i) & 1ull) : ((cv1 >> (i - 64)) & 1ull);
            bool conflict = (((st0 & sp0) | (st1 & sp1)) != 0ull) || cvbit;
            bool acc = isval && !conflict;
            bool schg = acc && (upper || !stbit);

            unsigned bInv = __ballot_sync(FULLMASK, !isval);
            int fI = bInv ? (__ffs(bInv) - 1) : 32;
            unsigned bS = __ballot_sync(FULLMASK, schg);
            if (fI < 32) bS &= (fI ? ((1u << fI) - 1u) : 0u);
            int fS = bS ? (__ffs(bS) - 1) : 32;
            int lim = fS < fI ? fS : fI;

            // finalized plain accepts (no state change) before first changer
            if (acc && lane < lim) rB[idx] = (float)av;

            if (fS < fI && fS < 32) {
                if (lane == fS) {
                    rB[idx] = (float)av;
                    if (i < 64) st0 |= (1ull << i); else st1 |= (1ull << (i - 64));
                    if (upper) { cv0 |= sp0; cv1 |= sp1; }
                }
                st0 = __shfl_sync(FULLMASK, st0, fS);
                st1 = __shfl_sync(FULLMASK, st1, fS);
                cv0 = __shfl_sync(FULLMASK, cv0, fS);
                cv1 = __shfl_sync(FULLMASK, cv1, fS);
                t += fS + 1;
            } else if (fI < 32) {
                break;  // sorted invalid tail reached
            } else {
                t += 32;
            }
        }
    }
}

// ============================================================================
extern "C" void kernel_launch(void* const* d_in, const int* in_sizes, int n_in,
                              void* d_out, int out_size) {
    (void)in_sizes; (void)n_in;
    const float* bert = (const float*)d_in[0];
    const int*   tagseq = (const int*)d_in[1];
    const float* wS = (const float*)d_in[2];
    const float* bS = (const float*)d_in[3];
    const float* wE = (const float*)d_in[4];
    const float* bE = (const float*)d_in[5];
    const float* Wb = (const float*)d_in[6];
    float* out = (float*)d_out;

    bool scoreInOut = (out_size >= SCORE_ELEMS);
    float* scorePtr = out;
    if (!scoreInOut) {
        void* p = nullptr;
        cudaGetSymbolAddress(&p, Sg);
        scorePtr = (float*)p;
    }

    proj_kernel<<<dim3(96, 2), 320>>>(bert, wS, bS, wE, bE);
    biaff_left<<<432, 320>>>(Wb);
    biaff_right<<<432, 256>>>(scorePtr);

    float* resPtr = nullptr;
    if (out_size >= SCORE_ELEMS + RESULT_ELEMS) resPtr = out + SCORE_ELEMS;
    else if (!scoreInOut && out_size >= RESULT_ELEMS) resPtr = out;

    if (resPtr) {
        cudaFuncSetAttribute(decode_kernel,
                             cudaFuncAttributeMaxDynamicSharedMemorySize, DEC_SMEM);
        decode_kernel<<<48, 1024, DEC_SMEM>>>(scorePtr, tagseq, resPtr);
    }
}

// round 4
// speedup vs baseline: 1.4288x; 1.2058x over previous
#include <cuda_runtime.h>
#include <cstdint>

// Problem constants
#define BB 48
#define LL 128
#define DD 1024
#define HH 150      // ffnn out
#define HP 151      // +bias col
#define OO 9
#define LDX 160     // padded feature stride (cols 151..159 zero)

#define N_CELLS (LL*LL)              // 16384
#define SCORE_ELEMS (BB*LL*LL*OO)    // 7077888
#define RESULT_ELEMS (BB*LL*LL)      // 786432

#define FULLMASK 0xFFFFFFFFu

// ---------------- static device scratch (no runtime allocation allowed) ------
__device__ float Xg[(size_t)BB*LL*LDX];               // [6144][160], col150=1, 151..159=0
__device__ float Yg[(size_t)BB*LL*LDX];
__device__ float Tg[(size_t)BB*OO*LL*LDX];            // [(b*9+o)][128][160]
__device__ float Sg[(size_t)SCORE_ELEMS];             // score in [b][o][x][y] layout

// ---------------- f32x2 helpers ---------------------------------------------
__device__ __forceinline__ void fma2(unsigned long long& d, unsigned long long a,
                                     unsigned long long b) {
    asm("fma.rn.f32x2 %0, %1, %2, %0;" : "+l"(d) : "l"(a), "l"(b));
}
__device__ __forceinline__ unsigned long long pack2(float x) {
    unsigned long long r;
    asm("mov.b64 %0, {%1, %1};" : "=l"(r) : "f"(x));
    return r;
}
__device__ __forceinline__ float2 unpack2(unsigned long long v) {
    float2 f;
    asm("mov.b64 {%0, %1}, %2;" : "=f"(f.x), "=f"(f.y) : "l"(v));
    return f;
}

// 8-row x 8-col (4 f32x2) micro step
__device__ __forceinline__ void micro_step8(const float* __restrict__ aRow,
                                            const float* __restrict__ bRow,
                                            unsigned long long acc[8][4]) {
    float4 a0 = *(const float4*)(aRow);
    float4 a1 = *(const float4*)(aRow + 4);
    ulonglong2 q0 = *(const ulonglong2*)(bRow);
    ulonglong2 q1 = *(const ulonglong2*)(bRow + 4);
    unsigned long long bb[4] = {q0.x, q0.y, q1.x, q1.y};
    float av[8] = {a0.x, a0.y, a0.z, a0.w, a1.x, a1.y, a1.z, a1.w};
#pragma unroll
    for (int r = 0; r < 8; r++) {
        unsigned long long ap = pack2(av[r]);
#pragma unroll
        for (int p = 0; p < 4; p++) fma2(acc[r][p], ap, bb[p]);
    }
}

// 4-row x 8-col micro step
__device__ __forceinline__ void micro_step4(const float* __restrict__ aRow,
                                            const float* __restrict__ bRow,
                                            unsigned long long acc[4][4]) {
    float4 a0 = *(const float4*)(aRow);
    ulonglong2 q0 = *(const ulonglong2*)(bRow);
    ulonglong2 q1 = *(const ulonglong2*)(bRow + 4);
    unsigned long long bb[4] = {q0.x, q0.y, q1.x, q1.y};
    float av[4] = {a0.x, a0.y, a0.z, a0.w};
#pragma unroll
    for (int r = 0; r < 4; r++) {
        unsigned long long ap = pack2(av[r]);
#pragma unroll
        for (int p = 0; p < 4; p++) fma2(acc[r][p], ap, bb[p]);
    }
}

// ============================================================================
// Kernel 1: projections.  X/Y[r][c] = bert[r]·w[c] + bias[c]; col150=1; pad=0
// grid (96, 2), block 320. Register-staged double-buffered k-loop.
// ============================================================================
__global__ __launch_bounds__(320) void proj_kernel(
    const float* __restrict__ bert,
    const float* __restrict__ wS, const float* __restrict__ bS,
    const float* __restrict__ wE, const float* __restrict__ bE) {
    const int z = blockIdx.y;
    const float* w    = z ? wE : wS;
    const float* bias = z ? bE : bS;
    float* outp       = z ? Yg : Xg;
    const int mBase = blockIdx.x * 64;

    __shared__ alignas(16) float As[16][68];
    __shared__ alignas(16) float Bs[16][164];

    const int t = threadIdx.x;
    const int tx = t % 20, ty = t / 20;

    // staging maps (constant per thread)
    int aRow[4], aKk[4]; bool aV[4];
#pragma unroll
    for (int s = 0; s < 4; s++) {
        int e = t + 320 * s;
        aV[s] = e < 64 * 16;
        aRow[s] = e >> 4; aKk[s] = e & 15;
    }
    int bC[8], bKk[8];
#pragma unroll
    for (int s = 0; s < 8; s++) {
        int e = t + 320 * s;
        bC[s] = e >> 4; bKk[s] = e & 15;
    }

    float aReg[4], bReg[8];
    auto loadT = [&](int k0) {
#pragma unroll
        for (int s = 0; s < 4; s++)
            aReg[s] = aV[s] ? bert[(size_t)(mBase + aRow[s]) * DD + k0 + aKk[s]] : 0.f;
#pragma unroll
        for (int s = 0; s < 8; s++)
            bReg[s] = (bC[s] < HH) ? w[(size_t)bC[s] * DD + k0 + bKk[s]] : 0.f;
    };

    unsigned long long acc[4][4];
#pragma unroll
    for (int r = 0; r < 4; r++)
#pragma unroll
        for (int p = 0; p < 4; p++) acc[r][p] = 0ull;

    loadT(0);
    for (int k0 = 0; k0 < DD; k0 += 16) {
#pragma unroll
        for (int s = 0; s < 4; s++) if (aV[s]) As[aKk[s]][aRow[s]] = aReg[s];
#pragma unroll
        for (int s = 0; s < 8; s++) Bs[bKk[s]][bC[s]] = bReg[s];
        __syncthreads();
        if (k0 + 16 < DD) loadT(k0 + 16);
#pragma unroll
        for (int kk = 0; kk < 16; kk++)
            micro_step4(&As[kk][ty * 4], &Bs[kk][tx * 8], acc);
        __syncthreads();
    }

#pragma unroll
    for (int r = 0; r < 4; r++) {
        int row = mBase + ty * 4 + r;
        float* orow = &outp[(size_t)row * LDX];
#pragma unroll
        for (int p = 0; p < 4; p++) {
            float2 v = unpack2(acc[r][p]);
            int c0 = tx * 8 + 2 * p;
            float o0 = (c0 < HH) ? v.x + bias[c0] : (c0 == HH ? 1.f : 0.f);
            int c1 = c0 + 1;
            float o1 = (c1 < HH) ? v.y + bias[c1] : (c1 == HH ? 1.f : 0.f);
            orow[c0] = o0;
            orow[c1] = o1;
        }
    }
}

// ============================================================================
// Kernel 2: T[(b,o)][x][j] = sum_i X[b][x][i] * W[o][i][j]    (K=160, pads 0)
// grid 432, block 320. Register-staged double-buffered.
// ============================================================================
__global__ __launch_bounds__(320) void biaff_left(const float* __restrict__ Wb) {
    const int blk = blockIdx.x;
    const int b = blk / OO, o = blk % OO;
    const float* Xb = &Xg[(size_t)b * LL * LDX];
    const float* Wo = Wb + (size_t)o * HP * HP;
    float* Tp = &Tg[(size_t)blk * LL * LDX];

    __shared__ alignas(16) float As[16][132];
    __shared__ alignas(16) float Bs[16][164];

    const int t = threadIdx.x;
    const int tx = t % 20, ty = t / 20;

    int aRow[7], aKk[7]; bool aV[7];
#pragma unroll
    for (int s = 0; s < 7; s++) {
        int e = t + 320 * s;
        aV[s] = e < 128 * 16;
        aRow[s] = e >> 4; aKk[s] = e & 15;
    }
    int bJ[8], bKk[8];
#pragma unroll
    for (int s = 0; s < 8; s++) {
        int e = t + 320 * s;
        bKk[s] = e / 160; bJ[s] = e % 160;
    }

    float aReg[7], bReg[8];
    auto loadT = [&](int k0) {
#pragma unroll
        for (int s = 0; s < 7; s++)
            aReg[s] = aV[s] ? Xb[(size_t)aRow[s] * LDX + k0 + aKk[s]] : 0.f;
#pragma unroll
        for (int s = 0; s < 8; s++) {
            int i = k0 + bKk[s];
            bReg[s] = (i < HP && bJ[s] < HP) ? Wo[(size_t)i * HP + bJ[s]] : 0.f;
        }
    };

    unsigned long long acc[8][4];
#pragma unroll
    for (int r = 0; r < 8; r++)
#pragma unroll
        for (int p = 0; p < 4; p++) acc[r][p] = 0ull;

    loadT(0);
    for (int k0 = 0; k0 < LDX; k0 += 16) {
#pragma unroll
        for (int s = 0; s < 7; s++) if (aV[s]) As[aKk[s]][aRow[s]] = aReg[s];
#pragma unroll
        for (int s = 0; s < 8; s++) Bs[bKk[s]][bJ[s]] = bReg[s];
        __syncthreads();
        if (k0 + 16 < LDX) loadT(k0 + 16);
#pragma unroll
        for (int kk = 0; kk < 16; kk++)
            micro_step8(&As[kk][ty * 8], &Bs[kk][tx * 8], acc);
        __syncthreads();
    }

#pragma unroll
    for (int r = 0; r < 8; r++) {
        float* orow = &Tp[(size_t)(ty * 8 + r) * LDX];
#pragma unroll
        for (int p = 0; p < 4; p++) {
            float2 v = unpack2(acc[r][p]);
            int c0 = tx * 8 + 2 * p;
            orow[c0] = v.x;
            orow[c0 + 1] = v.y;
        }
    }
}

// ============================================================================
// Kernel 3: Sg[(b*9+o)][x][y] = sum_j T[(b,o)][x][j] * Y[b][y][j]
// grid 432, block 256. Coalesced [b][o][x][y] stores.
// ============================================================================
__global__ __launch_bounds__(256, 2) void biaff_right() {
    const int blk = blockIdx.x;
    const int b = blk / OO;
    const float* Tp = &Tg[(size_t)blk * LL * LDX];
    const float* Yb = &Yg[(size_t)b * LL * LDX];

    __shared__ alignas(16) float As[16][132];
    __shared__ alignas(16) float Bs[16][132];

    const int t = threadIdx.x;
    const int tx = t % 16, ty = t / 16;

    int gRow[8], gKk[8];
#pragma unroll
    for (int s = 0; s < 8; s++) {
        int e = t + 256 * s;
        gRow[s] = e >> 4; gKk[s] = e & 15;
    }

    float aReg[8], bReg[8];
    auto loadT = [&](int k0) {
#pragma unroll
        for (int s = 0; s < 8; s++) {
            aReg[s] = Tp[(size_t)gRow[s] * LDX + k0 + gKk[s]];
            bReg[s] = Yb[(size_t)gRow[s] * LDX + k0 + gKk[s]];
        }
    };

    unsigned long long acc[8][4];
#pragma unroll
    for (int r = 0; r < 8; r++)
#pragma unroll
        for (int p = 0; p < 4; p++) acc[r][p] = 0ull;

    loadT(0);
    for (int k0 = 0; k0 < LDX; k0 += 16) {
#pragma unroll
        for (int s = 0; s < 8; s++) {
            As[gKk[s]][gRow[s]] = aReg[s];
            Bs[gKk[s]][gRow[s]] = bReg[s];
        }
        __syncthreads();
        if (k0 + 16 < LDX) loadT(k0 + 16);
#pragma unroll
        for (int kk = 0; kk < 16; kk++)
            micro_step8(&As[kk][ty * 8], &Bs[kk][tx * 8], acc);
        __syncthreads();
    }

#pragma unroll
    for (int r = 0; r < 8; r++) {
        int x = ty * 8 + r;
        float* orow = &Sg[((size_t)blk * LL + x) * LL];
        float2 v0 = unpack2(acc[r][0]);
        float2 v1 = unpack2(acc[r][1]);
        float2 v2 = unpack2(acc[r][2]);
        float2 v3 = unpack2(acc[r][3]);
        float4* dst = (float4*)(orow + tx * 8);
        dst[0] = make_float4(v0.x, v0.y, v1.x, v1.y);
        dst[1] = make_float4(v2.x, v2.y, v3.x, v3.y);
    }
}

// ============================================================================
// Kernel 3b: transpose Sg [b][o][x][y] -> out [b][x][y][o]. Fully coalesced.
// grid 1536, block 256. 512 cells/block.
// ============================================================================
#define TP_CELLS 512
__global__ __launch_bounds__(256) void transpose_kernel(float* __restrict__ out) {
    __shared__ float tile[OO][TP_CELLS + 1];
    const size_t cb = (size_t)blockIdx.x * TP_CELLS;
    const int b = (int)(cb / N_CELLS);
    const int off = (int)(cb % N_CELLS);
    const float* src = Sg + (size_t)b * OO * N_CELLS + off;
    for (int w = threadIdx.x; w < OO * TP_CELLS; w += 256) {
        int o = w / TP_CELLS, c = w % TP_CELLS;
        tile[o][c] = src[(size_t)o * N_CELLS + c];
    }
    __syncthreads();
    float* dst = out + cb * OO;
    for (int q = threadIdx.x; q < OO * TP_CELLS; q += 256) {
        dst[q] = tile[q % OO][q / OO];
    }
}

// ============================================================================
// Kernel 4: per-sentence greedy decode (radix sort + speculative scan).
// grid 48, block 1024. Dynamic smem layout (bytes):
//   [0,      65536)  keyA  u32[16384]
//   [65536, 131072)  keyB  u32[16384]
//   [131072,163840)  payA  u16[16384]
//   [163840,196608)  payB  u16[16384]
//   [196608,212992)  hist  u16[8192]   (digit-major: h = d*32 + warp)
//   [212992,229376)  ans   u8[16384]
//   [229376,229504)  scanW u32[32]
// ============================================================================
#define DEC_SMEM 229504

__device__ __forceinline__ unsigned long long rmask64(int lo, int hi) {
    unsigned long long m = (hi >= 63) ? ~0ull : ((1ull << (hi + 1)) - 1ull);
    return m & (~0ull << lo);
}

__global__ __launch_bounds__(1024) void decode_kernel(
    const int* __restrict__ tagseq,
    float* __restrict__ resOut) {
    const int b = blockIdx.x;
    const int tid = threadIdx.x;
    const int wrp = tid >> 5, lane = tid & 31;
    const unsigned laneLT = (lane == 0) ? 0u : ((1u << lane) - 1u);

    extern __shared__ char smdyn[];
    unsigned* keyA = (unsigned*)(smdyn);
    unsigned* keyB = (unsigned*)(smdyn + 65536);
    unsigned short* payA = (unsigned short*)(smdyn + 131072);
    unsigned short* payB = (unsigned short*)(smdyn + 163840);
    unsigned short* hist = (unsigned short*)(smdyn + 196608);
    unsigned char* ansS = (unsigned char*)(smdyn + 212992);
    unsigned* scanW = (unsigned*)(smdyn + 229376);

    const float* sB = Sg + (size_t)b * OO * N_CELLS;  // [o][16384]
    const int* mB = tagseq + (size_t)b * N_CELLS;
    float* rB = resOut + (size_t)b * N_CELLS;

    // ---- Phase 1: argmax over O (o-major coalesced), keys, result init -----
    for (int idx = tid; idx < N_CELLS; idx += 1024) {
        float best = sB[idx];
        int bo = 0;
#pragma unroll
        for (int o = 1; o < OO; o++) {
            float v = sB[(size_t)o * N_CELLS + idx];
            if (v > best) { best = v; bo = o; }
        }
        ansS[idx] = (unsigned char)bo;
        bool valid = (bo != 1) && (mB[idx] > 0);
        unsigned u = __float_as_uint(best);
        u ^= (u & 0x80000000u) ? 0xFFFFFFFFu : 0x80000000u;  // ascending-orderable
        unsigned ud = ~u;                                    // descending-orderable
        if (!valid) ud = 0xFFFFFFFFu;
        keyA[idx] = ud;
        payA[idx] = (unsigned short)idx;
        rB[idx] = 1.0f;  // NON_ENTITY
    }
    __syncthreads();

    // ---- Phase 2: stable LSD radix sort, 4x8-bit passes --------------------
    const int chunk = wrp * 512;
#pragma unroll
    for (int pass = 0; pass < 4; pass++) {
        const int shift = pass * 8;
        unsigned* srcK = (pass & 1) ? keyB : keyA;
        unsigned* dstK = (pass & 1) ? keyA : keyB;
        unsigned short* srcP = (pass & 1) ? payB : payA;
        unsigned short* dstP = (pass & 1) ? payA : payB;

        for (int h = tid; h < 8192; h += 1024) hist[h] = 0;
        __syncthreads();

#pragma unroll 4
        for (int r = 0; r < 16; r++) {
            unsigned k = srcK[chunk + r * 32 + lane];
            unsigned d = (k >> shift) & 255u;
            unsigned m = __match_any_sync(FULLMASK, d);
            if ((m & laneLT) == 0)
                hist[d * 32 + wrp] = (unsigned short)(hist[d * 32 + wrp] + __popc(m));
        }
        __syncthreads();

        {
            int h0 = tid * 8;
            unsigned short loc[8];
            unsigned s = 0;
#pragma unroll
            for (int q = 0; q < 8; q++) { loc[q] = hist[h0 + q]; s += loc[q]; }
            unsigned v = s;
#pragma unroll
            for (int off = 1; off < 32; off <<= 1) {
                unsigned n = __shfl_up_sync(FULLMASK, v, off);
                if (lane >= off) v += n;
            }
            if (lane == 31) scanW[wrp] = v;
            __syncthreads();
            if (tid < 32) {
                unsigned wv = scanW[tid];
                unsigned iv = wv;
#pragma unroll
                for (int off = 1; off < 32; off <<= 1) {
                    unsigned n = __shfl_up_sync(FULLMASK, iv, off);
                    if (tid >= off) iv += n;
                }
                scanW[tid] = iv - wv;
            }
            __syncthreads();
            unsigned run = scanW[wrp] + (v - s);
#pragma unroll
            for (int q = 0; q < 8; q++) {
                unsigned c = loc[q];
                hist[h0 + q] = (unsigned short)run;
                run += c;
            }
        }
        __syncthreads();

#pragma unroll 4
        for (int r = 0; r < 16; r++) {
            int idx = chunk + r * 32 + lane;
            unsigned k = srcK[idx];
            unsigned short p = srcP[idx];
            unsigned d = (k >> shift) & 255u;
            unsigned m = __match_any_sync(FULLMASK, d);
            int rank = __popc(m & laneLT);
            int leaderLane = __ffs(m) - 1;
            unsigned baseOff = 0;
            if (lane == leaderLane) {
                baseOff = hist[d * 32 + wrp];
                hist[d * 32 + wrp] = (unsigned short)(baseOff + __popc(m));
            }
            baseOff = __shfl_sync(FULLMASK, baseOff, leaderLane);
            dstK[baseOff + rank] = k;
            dstP[baseOff + rank] = p;
        }
        __syncthreads();
    }
    // sorted result in keyA / payA

    // ---- Phase 3: warp 0 speculative greedy scan, 64-item windows ----------
    if (tid < 32) {
        unsigned long long st0 = 0, st1 = 0, cv0 = 0, cv1 = 0;
        int t = 0;
        while (t < N_CELLS) {
            int myA = t + lane, myB = t + 32 + lane;
            unsigned udA = (myA < N_CELLS) ? keyA[myA] : 0xFFFFFFFFu;
            unsigned udB = (myB < N_CELLS) ? keyA[myB] : 0xFFFFFFFFu;
            int idxA = (myA < N_CELLS) ? (int)payA[myA] : 0;
            int idxB = (myB < N_CELLS) ? (int)payA[myB] : 0;
            bool valA = (udA != 0xFFFFFFFFu);
            bool valB = (udB != 0xFFFFFFFFu);
            int iA = idxA >> 7, jA = idxA & 127;
            int iB = idxB >> 7, jB = idxB & 127;
            int avA = (int)ansS[idxA];
            int avB = (int)ansS[idxB];

            bool upA = (jA >= iA), upB = (jB >= iB);
            unsigned long long sA0 = 0, sA1 = 0, sB0 = 0, sB1 = 0;
            if (upA) {
                if (iA <= 63) sA0 = rmask64(iA, jA < 63 ? jA : 63);
                if (jA >= 64) sA1 = rmask64(iA > 64 ? iA - 64 : 0, jA - 64);
            }
            if (upB) {
                if (iB <= 63) sB0 = rmask64(iB, jB < 63 ? jB : 63);
                if (jB >= 64) sB1 = rmask64(iB > 64 ? iB - 64 : 0, jB - 64);
            }
            bool stA = (iA < 64) ? ((st0 >> iA) & 1ull) : ((st1 >> (iA - 64)) & 1ull);
            bool cvA = (iA < 64) ? ((cv0 >> iA) & 1ull) : ((cv1 >> (iA - 64)) & 1ull);
            bool stB = (iB < 64) ? ((st0 >> iB) & 1ull) : ((st1 >> (iB - 64)) & 1ull);
            bool cvB = (iB < 64) ? ((cv0 >> iB) & 1ull) : ((cv1 >> (iB - 64)) & 1ull);
            bool accA = valA && !((((st0 & sA0) | (st1 & sA1)) != 0ull) || cvA);
            bool accB = valB && !((((st0 & sB0) | (st1 & sB1)) != 0ull) || cvB);
            bool schgA = accA && (upA || !stA);
            bool schgB = accB && (upB || !stB);

            unsigned long long bInv =
                (unsigned long long)__ballot_sync(FULLMASK, !valA) |
                ((unsigned long long)__ballot_sync(FULLMASK, !valB) << 32);
            unsigned long long bS =
                (unsigned long long)__ballot_sync(FULLMASK, schgA) |
                ((unsigned long long)__ballot_sync(FULLMASK, schgB) << 32);
            int fI = bInv ? (__ffsll((long long)bInv) - 1) : 64;
            if (fI < 64) bS &= (fI ? ((1ull << fI) - 1ull) : 0ull);
            int fS = bS ? (__ffsll((long long)bS) - 1) : 64;
            int lim = fS < fI ? fS : fI;

            if (accA && lane < lim) rB[idxA] = (float)avA;
            if (accB && 32 + lane < lim) rB[idxB] = (float)avB;

            if (fS < fI && fS < 64) {
                int sl = fS & 31;
                bool second = fS >= 32;
                if (lane == sl) {
                    int i = second ? iB : iA;
                    bool up = second ? upB : upA;
                    unsigned long long p0 = second ? sB0 : sA0;
                    unsigned long long p1 = second ? sB1 : sA1;
                    rB[second ? idxB : idxA] = (float)(second ? avB : avA);
                    if (i < 64) st0 |= (1ull << i); else st1 |= (1ull << (i - 64));
                    if (up) { cv0 |= p0; cv1 |= p1; }
                }
                st0 = __shfl_sync(FULLMASK, st0, sl);
                st1 = __shfl_sync(FULLMASK, st1, sl);
                cv0 = __shfl_sync(FULLMASK, cv0, sl);
                cv1 = __shfl_sync(FULLMASK, cv1, sl);
                t += fS + 1;
            } else if (fI < 64) {
                break;
            } else {
                t += 64;
            }
        }
    }
}

// ============================================================================
extern "C" void kernel_launch(void* const* d_in, const int* in_sizes, int n_in,
                              void* d_out, int out_size) {
    (void)in_sizes; (void)n_in;
    const float* bert = (const float*)d_in[0];
    const int*   tagseq = (const int*)d_in[1];
    const float* wS = (const float*)d_in[2];
    const float* bS = (const float*)d_in[3];
    const float* wE = (const float*)d_in[4];
    const float* bE = (const float*)d_in[5];
    const float* Wb = (const float*)d_in[6];
    float* out = (float*)d_out;

    proj_kernel<<<dim3(96, 2), 320>>>(bert, wS, bS, wE, bE);
    biaff_left<<<432, 320>>>(Wb);
    biaff_right<<<432, 256>>>();

    bool scoreInOut = (out_size >= SCORE_ELEMS);
    if (scoreInOut)
        transpose_kernel<<<RESULT_ELEMS / TP_CELLS, 256>>>(out);

    float* resPtr = nullptr;
    if (out_size >= SCORE_ELEMS + RESULT_ELEMS) resPtr = out + SCORE_ELEMS;
    else if (!scoreInOut && out_size >= RESULT_ELEMS) resPtr = out;

    if (resPtr) {
        cudaFuncSetAttribute(decode_kernel,
                             cudaFuncAttributeMaxDynamicSharedMemorySize, DEC_SMEM);
        decode_kernel<<<48, 1024, DEC_SMEM>>>(tagseq, resPtr);
    }
}

// round 6
// speedup vs baseline: 1.5574x; 1.0900x over previous
#include <cuda_runtime.h>
#include <cstdint>

// Problem constants
#define BB 48
#define LL 128
#define DD 1024
#define HH 150      // ffnn out
#define HP 151      // +bias col
#define OO 9
#define LDX 160     // padded feature stride

#define N_CELLS (LL*LL)              // 16384
#define SCORE_ELEMS (BB*LL*LL*OO)    // 7077888
#define RESULT_ELEMS (BB*LL*LL)      // 786432
#define UCOLS (OO*LDX)               // 1440

#define FULLMASK 0xFFFFFFFFu

// ---------------- static device scratch --------------------------------------
__device__ float Xg[(size_t)BB*LL*LDX];               // [6144][160]
__device__ float Yg[(size_t)BB*LL*LDX];
__device__ float Ug[(size_t)BB*LL*UCOLS];             // [6144][1440] = [b,x][o*160+j]
__device__ float Sg[(size_t)SCORE_ELEMS];             // [(b*128+x)*9+o][128] = [b][x][o][y]
__device__ float Wpad[(size_t)OO*LDX*LDX];            // [9][160][160] zero-padded W

// ---------------- f32x2 helpers ---------------------------------------------
__device__ __forceinline__ void fma2(unsigned long long& d, unsigned long long a,
                                     unsigned long long b) {
    asm("fma.rn.f32x2 %0, %1, %2, %0;" : "+l"(d) : "l"(a), "l"(b));
}
__device__ __forceinline__ unsigned long long pack2(float x) {
    unsigned long long r;
    asm("mov.b64 %0, {%1, %1};" : "=l"(r) : "f"(x));
    return r;
}
__device__ __forceinline__ float2 unpack2(unsigned long long v) {
    float2 f;
    asm("mov.b64 {%0, %1}, %2;" : "=f"(f.x), "=f"(f.y) : "l"(v));
    return f;
}

// 8-row x 8-col micro step
__device__ __forceinline__ void micro_step8(const float* __restrict__ aRow,
                                            const float* __restrict__ bRow,
                                            unsigned long long acc[8][4]) {
    float4 a0 = *(const float4*)(aRow);
    float4 a1 = *(const float4*)(aRow + 4);
    ulonglong2 q0 = *(const ulonglong2*)(bRow);
    ulonglong2 q1 = *(const ulonglong2*)(bRow + 4);
    unsigned long long bb[4] = {q0.x, q0.y, q1.x, q1.y};
    float av[8] = {a0.x, a0.y, a0.z, a0.w, a1.x, a1.y, a1.z, a1.w};
#pragma unroll
    for (int r = 0; r < 8; r++) {
        unsigned long long ap = pack2(av[r]);
#pragma unroll
        for (int p = 0; p < 4; p++) fma2(acc[r][p], ap, bb[p]);
    }
}

// 16-row x 8-col micro step
__device__ __forceinline__ void micro_step16(const float* __restrict__ aRow,
                                             const float* __restrict__ bRow,
                                             unsigned long long acc[16][4]) {
    float4 a0 = *(const float4*)(aRow);
    float4 a1 = *(const float4*)(aRow + 4);
    float4 a2 = *(const float4*)(aRow + 8);
    float4 a3 = *(const float4*)(aRow + 12);
    ulonglong2 q0 = *(const ulonglong2*)(bRow);
    ulonglong2 q1 = *(const ulonglong2*)(bRow + 4);
    unsigned long long bb[4] = {q0.x, q0.y, q1.x, q1.y};
    float av[16] = {a0.x, a0.y, a0.z, a0.w, a1.x, a1.y, a1.z, a1.w,
                    a2.x, a2.y, a2.z, a2.w, a3.x, a3.y, a3.z, a3.w};
#pragma unroll
    for (int r = 0; r < 16; r++) {
        unsigned long long ap = pack2(av[r]);
#pragma unroll
        for (int p = 0; p < 4; p++) fma2(acc[r][p], ap, bb[p]);
    }
}

// ============================================================================
// Kernel 0: pad W [9][151][151] -> Wpad [9][160][160] (zeros elsewhere)
// ============================================================================
__global__ __launch_bounds__(256) void pad_w_kernel(const float* __restrict__ Wb) {
    int idx = blockIdx.x * 256 + threadIdx.x;
    if (idx >= OO * LDX * LDX) return;
    int o = idx / (LDX * LDX);
    int r = idx % (LDX * LDX);
    int i = r / LDX, j = r % LDX;
    Wpad[idx] = (i < HP && j < HP) ? Wb[(size_t)o * HP * HP + i * HP + j] : 0.f;
}

// ============================================================================
// Kernel 1: projections. tile 64x160, block 160 (ty=t/20 rows-of-8, tx=t%20),
// per-thread 8x8, k-tile 16, float4-staged double buffering.
// grid (96, 2)
// ============================================================================
__global__ __launch_bounds__(160, 2) void proj_kernel(
    const float* __restrict__ bert,
    const float* __restrict__ wS, const float* __restrict__ bS,
    const float* __restrict__ wE, const float* __restrict__ bE) {
    const int z = blockIdx.y;
    const float* w    = z ? wE : wS;
    const float* bias = z ? bE : bS;
    float* outp       = z ? Yg : Xg;
    const int mBase = blockIdx.x * 64;

    __shared__ alignas(16) float As[16][72];
    __shared__ alignas(16) float Bs[16][168];

    const int t = threadIdx.x;
    const int tx = t % 20, ty = t / 20;

    // A staging: 64*16/4 = 256 float4, 2 slots (slot1 valid if t<96)
    // B staging: 160*16/4 = 640 float4, 4 slots
    const int aRow0 = t >> 2, aRow1 = (t + 160) >> 2;
    const bool aV1 = (t < 96);
    const int kq = t & 3;
    int bCol[4];
#pragma unroll
    for (int s = 0; s < 4; s++) bCol[s] = (t + 160 * s) >> 2;

    float4 aF[2], bF[4];
    const float4 z4 = make_float4(0.f, 0.f, 0.f, 0.f);
    auto loadT = [&](int k0) {
        aF[0] = *(const float4*)(bert + (size_t)(mBase + aRow0) * DD + k0 + kq * 4);
        aF[1] = aV1 ? *(const float4*)(bert + (size_t)(mBase + aRow1) * DD + k0 + kq * 4) : z4;
#pragma unroll
        for (int s = 0; s < 4; s++)
            bF[s] = (bCol[s] < HH)
                  ? *(const float4*)(w + (size_t)bCol[s] * DD + k0 + kq * 4) : z4;
    };

    unsigned long long acc[8][4];
#pragma unroll
    for (int r = 0; r < 8; r++)
#pragma unroll
        for (int p = 0; p < 4; p++) acc[r][p] = 0ull;

    loadT(0);
    for (int k0 = 0; k0 < DD; k0 += 16) {
        {
            const float* f = (const float*)&aF[0];
#pragma unroll
            for (int c = 0; c < 4; c++) As[kq * 4 + c][aRow0] = f[c];
        }
        if (aV1) {
            const float* f = (const float*)&aF[1];
#pragma unroll
            for (int c = 0; c < 4; c++) As[kq * 4 + c][aRow1] = f[c];
        }
#pragma unroll
        for (int s = 0; s < 4; s++) {
            const float* f = (const float*)&bF[s];
#pragma unroll
            for (int c = 0; c < 4; c++) Bs[kq * 4 + c][bCol[s]] = f[c];
        }
        __syncthreads();
        if (k0 + 16 < DD) loadT(k0 + 16);
#pragma unroll
        for (int kk = 0; kk < 16; kk++)
            micro_step8(&As[kk][ty * 8], &Bs[kk][tx * 8], acc);
        __syncthreads();
    }

#pragma unroll
    for (int r = 0; r < 8; r++) {
        int row = mBase + ty * 8 + r;
        float* orow = &outp[(size_t)row * LDX];
#pragma unroll
        for (int p = 0; p < 4; p++) {
            float2 v = unpack2(acc[r][p]);
            int c0 = tx * 8 + 2 * p;
            float o0 = (c0 < HH) ? v.x + bias[c0] : (c0 == HH ? 1.f : 0.f);
            int c1 = c0 + 1;
            float o1 = (c1 < HH) ? v.y + bias[c1] : (c1 == HH ? 1.f : 0.f);
            orow[c0] = o0;
            orow[c1] = o1;
        }
    }
}

// ============================================================================
// Kernel 2: Ug[6144][1440] = Xg[6144][160] @ Wpad (one big GEMM).
// Tile 128x160 (N-tile = one o). grid (48, 9), block 160, per-thread 16x8.
// ============================================================================
__global__ __launch_bounds__(160, 2) void biaff_left() {
    const int mBase = blockIdx.x * 128;
    const int o = blockIdx.y;
    const float* Wo = Wpad + (size_t)o * LDX * LDX;

    __shared__ alignas(16) float As[16][136];
    __shared__ alignas(16) float Bs[16][168];

    const int t = threadIdx.x;
    const int tx = t % 20, ty = t / 20;
    const int kq = t & 3;

    // A: 128*16/4 = 512 f4, 4 slots (slot3 valid if t<32). rows f>>2
    int aRow[4]; bool aV[4];
#pragma unroll
    for (int s = 0; s < 4; s++) { int f = t + 160 * s; aV[s] = f < 512; aRow[s] = f >> 2; }
    // B: 160*16/4 = 640 f4, 4 slots. f -> jq = f%40, kk = f/40
    int bJq[4], bKk[4];
#pragma unroll
    for (int s = 0; s < 4; s++) { int f = t + 160 * s; bJq[s] = f % 40; bKk[s] = f / 40; }

    float4 aF[4], bF[4];
    auto loadT = [&](int k0) {
#pragma unroll
        for (int s = 0; s < 4; s++)
            if (aV[s])
                aF[s] = *(const float4*)(Xg + (size_t)(mBase + aRow[s]) * LDX + k0 + kq * 4);
#pragma unroll
        for (int s = 0; s < 4; s++)
            bF[s] = *(const float4*)(Wo + (size_t)(k0 + bKk[s]) * LDX + bJq[s] * 4);
    };

    unsigned long long acc[16][4];
#pragma unroll
    for (int r = 0; r < 16; r++)
#pragma unroll
        for (int p = 0; p < 4; p++) acc[r][p] = 0ull;

    loadT(0);
    for (int k0 = 0; k0 < LDX; k0 += 16) {
#pragma unroll
        for (int s = 0; s < 4; s++) {
            if (aV[s]) {
                const float* f = (const float*)&aF[s];
#pragma unroll
                for (int c = 0; c < 4; c++) As[kq * 4 + c][aRow[s]] = f[c];
            }
        }
#pragma unroll
        for (int s = 0; s < 4; s++) {
            const float* f = (const float*)&bF[s];
#pragma unroll
            for (int c = 0; c < 4; c++) Bs[bKk[s]][bJq[s] * 4 + c] = f[c];
        }
        __syncthreads();
        if (k0 + 16 < LDX) loadT(k0 + 16);
#pragma unroll
        for (int kk = 0; kk < 16; kk++)
            micro_step16(&As[kk][ty * 16], &Bs[kk][tx * 8], acc);
        __syncthreads();
    }

#pragma unroll
    for (int r = 0; r < 16; r++) {
        int row = mBase + ty * 16 + r;
        float* orow = &Ug[(size_t)row * UCOLS + o * LDX + tx * 8];
        float2 v0 = unpack2(acc[r][0]);
        float2 v1 = unpack2(acc[r][1]);
        float2 v2 = unpack2(acc[r][2]);
        float2 v3 = unpack2(acc[r][3]);
        ((float4*)orow)[0] = make_float4(v0.x, v0.y, v1.x, v1.y);
        ((float4*)orow)[1] = make_float4(v2.x, v2.y, v3.x, v3.y);
    }
}

// ============================================================================
// Kernel 3: per b: Sg rows (b*1152 + g), g=(x*9+o):  C[g][y] = Ug_row(g) · Y[b][y]
// grid (9, 48) = (Mtile, b), block 128 (ty=t/16, tx=t%16), per-thread 16x8.
// ============================================================================
__global__ __launch_bounds__(128, 2) void biaff_right() {
    const int mBase = blockIdx.x * 128;   // row in [0,1152)
    const int b = blockIdx.y;
    const float* Yb = &Yg[(size_t)b * LL * LDX];

    __shared__ alignas(16) float As[16][136];
    __shared__ alignas(16) float Bs[16][136];

    const int t = threadIdx.x;
    const int tx = t % 16, ty = t / 16;
    const int kq = t & 3;

    // A: 4 slots exact: f = t+128s, row = f>>2
    size_t aOff[4];
    int aRow[4];
#pragma unroll
    for (int s = 0; s < 4; s++) {
        int f = t + 128 * s;
        aRow[s] = f >> 2;
        int g = mBase + aRow[s];
        int x = g / 9, oo = g % 9;
        aOff[s] = ((size_t)b * LL + x) * UCOLS + (size_t)oo * LDX;
    }
    // B: 4 slots exact: y = f>>2
    int bY[4];
#pragma unroll
    for (int s = 0; s < 4; s++) bY[s] = (t + 128 * s) >> 2;

    float4 aF[4], bF[4];
    auto loadT = [&](int k0) {
#pragma unroll
        for (int s = 0; s < 4; s++)
            aF[s] = *(const float4*)(Ug + aOff[s] + k0 + kq * 4);
#pragma unroll
        for (int s = 0; s < 4; s++)
            bF[s] = *(const float4*)(Yb + (size_t)bY[s] * LDX + k0 + kq * 4);
    };

    unsigned long long acc[16][4];
#pragma unroll
    for (int r = 0; r < 16; r++)
#pragma unroll
        for (int p = 0; p < 4; p++) acc[r][p] = 0ull;

    loadT(0);
    for (int k0 = 0; k0 < LDX; k0 += 16) {
#pragma unroll
        for (int s = 0; s < 4; s++) {
            const float* f = (const float*)&aF[s];
#pragma unroll
            for (int c = 0; c < 4; c++) As[kq * 4 + c][aRow[s]] = f[c];
        }
#pragma unroll
        for (int s = 0; s < 4; s++) {
            const float* f = (const float*)&bF[s];
#pragma unroll
            for (int c = 0; c < 4; c++) Bs[kq * 4 + c][bY[s]] = f[c];
        }
        __syncthreads();
        if (k0 + 16 < LDX) loadT(k0 + 16);
#pragma unroll
        for (int kk = 0; kk < 16; kk++)
            micro_step16(&As[kk][ty * 16], &Bs[kk][tx * 8], acc);
        __syncthreads();
    }

#pragma unroll
    for (int r = 0; r < 16; r++) {
        int g = mBase + ty * 16 + r;
        float* orow = &Sg[((size_t)b * 1152 + g) * LL + tx * 8];
        float2 v0 = unpack2(acc[r][0]);
        float2 v1 = unpack2(acc[r][1]);
        float2 v2 = unpack2(acc[r][2]);
        float2 v3 = unpack2(acc[r][3]);
        ((float4*)orow)[0] = make_float4(v0.x, v0.y, v1.x, v1.y);
        ((float4*)orow)[1] = make_float4(v2.x, v2.y, v3.x, v3.y);
    }
}

// ============================================================================
// Kernel 3b: transpose Sg [b][x][o][y] -> out [b][x][y][o]. 4 x-rows/block.
// grid 1536, block 256.
// ============================================================================
__global__ __launch_bounds__(256) void transpose_kernel(float* __restrict__ out) {
    __shared__ float tile[4][OO][132];
    const size_t base = (size_t)blockIdx.x * 4 * 1152;  // 4 x-rows of 9*128
    const float* src = Sg + base;
    for (int e = threadIdx.x; e < 4 * 1152; e += 256) {
        int xr = e / 1152, rem = e % 1152;
        tile[xr][rem >> 7][rem & 127] = src[e];
    }
    __syncthreads();
    float* dst = out + base;  // same flat offset: (b*128+x)*1152
    for (int q = threadIdx.x; q < 4 * 1152; q += 256) {
        int xr = q / 1152, rem = q % 1152;
        int y = rem / 9, o = rem % 9;
        dst[q] = tile[xr][o][y];
    }
}

// ============================================================================
// Kernel 4: per-sentence greedy decode (radix sort + speculative scan).
// grid 48, block 1024. smem layout unchanged (229504 B).
// ============================================================================
#define DEC_SMEM 229504

__device__ __forceinline__ unsigned long long rmask64(int lo, int hi) {
    unsigned long long m = (hi >= 63) ? ~0ull : ((1ull << (hi + 1)) - 1ull);
    return m & (~0ull << lo);
}

__global__ __launch_bounds__(1024) void decode_kernel(
    const int* __restrict__ tagseq,
    float* __restrict__ resOut) {
    const int b = blockIdx.x;
    const int tid = threadIdx.x;
    const int wrp = tid >> 5, lane = tid & 31;
    const unsigned laneLT = (lane == 0) ? 0u : ((1u << lane) - 1u);

    extern __shared__ char smdyn[];
    unsigned* keyA = (unsigned*)(smdyn);
    unsigned* keyB = (unsigned*)(smdyn + 65536);
    unsigned short* payA = (unsigned short*)(smdyn + 131072);
    unsigned short* payB = (unsigned short*)(smdyn + 163840);
    unsigned short* hist = (unsigned short*)(smdyn + 196608);
    unsigned char* ansS = (unsigned char*)(smdyn + 212992);
    unsigned* scanW = (unsigned*)(smdyn + 229376);

    const float* sB = Sg + (size_t)b * 1152 * LL;  // [x][o][y]
    const int* mB = tagseq + (size_t)b * N_CELLS;
    float* rB = resOut + (size_t)b * N_CELLS;

    // ---- Phase 1: argmax over O, keys, result init -------------------------
    for (int idx = tid; idx < N_CELLS; idx += 1024) {
        int x = idx >> 7, y = idx & 127;
        const float* base = sB + (size_t)x * 1152 + y;
        float best = base[0];
        int bo = 0;
#pragma unroll
        for (int o = 1; o < OO; o++) {
            float v = base[(size_t)o * LL];
            if (v > best) { best = v; bo = o; }
        }
        ansS[idx] = (unsigned char)bo;
        bool valid = (bo != 1) && (mB[idx] > 0);
        unsigned u = __float_as_uint(best);
        u ^= (u & 0x80000000u) ? 0xFFFFFFFFu : 0x80000000u;
        unsigned ud = ~u;
        if (!valid) ud = 0xFFFFFFFFu;
        keyA[idx] = ud;
        payA[idx] = (unsigned short)idx;
        rB[idx] = 1.0f;
    }
    __syncthreads();

    // ---- Phase 2: stable LSD radix sort, 4x8-bit passes --------------------
    const int chunk = wrp * 512;
#pragma unroll
    for (int pass = 0; pass < 4; pass++) {
        const int shift = pass * 8;
        unsigned* srcK = (pass & 1) ? keyB : keyA;
        unsigned* dstK = (pass & 1) ? keyA : keyB;
        unsigned short* srcP = (pass & 1) ? payB : payA;
        unsigned short* dstP = (pass & 1) ? payA : payB;

        for (int h = tid; h < 8192; h += 1024) hist[h] = 0;
        __syncthreads();

#pragma unroll 4
        for (int r = 0; r < 16; r++) {
            unsigned k = srcK[chunk + r * 32 + lane];
            unsigned d = (k >> shift) & 255u;
            unsigned m = __match_any_sync(FULLMASK, d);
            if ((m & laneLT) == 0)
                hist[d * 32 + wrp] = (unsigned short)(hist[d * 32 + wrp] + __popc(m));
        }
        __syncthreads();

        {
            int h0 = tid * 8;
            unsigned short loc[8];
            unsigned s = 0;
#pragma unroll
            for (int q = 0; q < 8; q++) { loc[q] = hist[h0 + q]; s += loc[q]; }
            unsigned v = s;
#pragma unroll
            for (int off = 1; off < 32; off <<= 1) {
                unsigned n = __shfl_up_sync(FULLMASK, v, off);
                if (lane >= off) v += n;
            }
            if (lane == 31) scanW[wrp] = v;
            __syncthreads();
            if (tid < 32) {
                unsigned wv = scanW[tid];
                unsigned iv = wv;
#pragma unroll
                for (int off = 1; off < 32; off <<= 1) {
                    unsigned n = __shfl_up_sync(FULLMASK, iv, off);
                    if (tid >= off) iv += n;
                }
                scanW[tid] = iv - wv;
            }
            __syncthreads();
            unsigned run = scanW[wrp] + (v - s);
#pragma unroll
            for (int q = 0; q < 8; q++) {
                unsigned c = loc[q];
                hist[h0 + q] = (unsigned short)run;
                run += c;
            }
        }
        __syncthreads();

#pragma unroll 4
        for (int r = 0; r < 16; r++) {
            int idx = chunk + r * 32 + lane;
            unsigned k = srcK[idx];
            unsigned short p = srcP[idx];
            unsigned d = (k >> shift) & 255u;
            unsigned m = __match_any_sync(FULLMASK, d);
            int rank = __popc(m & laneLT);
            int leaderLane = __ffs(m) - 1;
            unsigned baseOff = 0;
            if (lane == leaderLane) {
                baseOff = hist[d * 32 + wrp];
                hist[d * 32 + wrp] = (unsigned short)(baseOff + __popc(m));
            }
            baseOff = __shfl_sync(FULLMASK, baseOff, leaderLane);
            dstK[baseOff + rank] = k;
            dstP[baseOff + rank] = p;
        }
        __syncthreads();
    }

    // ---- Phase 3: warp 0 speculative greedy scan, 64-item windows ----------
    if (tid < 32) {
        unsigned long long st0 = 0, st1 = 0, cv0 = 0, cv1 = 0;
        int t = 0;
        while (t < N_CELLS) {
            int myA = t + lane, myB = t + 32 + lane;
            unsigned udA = (myA < N_CELLS) ? keyA[myA] : 0xFFFFFFFFu;
            unsigned udB = (myB < N_CELLS) ? keyA[myB] : 0xFFFFFFFFu;
            int idxA = (myA < N_CELLS) ? (int)payA[myA] : 0;
            int idxB = (myB < N_CELLS) ? (int)payA[myB] : 0;
            bool valA = (udA != 0xFFFFFFFFu);
            bool valB = (udB != 0xFFFFFFFFu);
            int iA = idxA >> 7, jA = idxA & 127;
            int iB = idxB >> 7, jB = idxB & 127;
            int avA = (int)ansS[idxA];
            int avB = (int)ansS[idxB];

            bool upA = (jA >= iA), upB = (jB >= iB);
            unsigned long long sA0 = 0, sA1 = 0, sB0 = 0, sB1 = 0;
            if (upA) {
                if (iA <= 63) sA0 = rmask64(iA, jA < 63 ? jA : 63);
                if (jA >= 64) sA1 = rmask64(iA > 64 ? iA - 64 : 0, jA - 64);
            }
            if (upB) {
                if (iB <= 63) sB0 = rmask64(iB, jB < 63 ? jB : 63);
                if (jB >= 64) sB1 = rmask64(iB > 64 ? iB - 64 : 0, jB - 64);
            }
            bool stA = (iA < 64) ? ((st0 >> iA) & 1ull) : ((st1 >> (iA - 64)) & 1ull);
            bool cvA = (iA < 64) ? ((cv0 >> iA) & 1ull) : ((cv1 >> (iA - 64)) & 1ull);
            bool stB = (iB < 64) ? ((st0 >> iB) & 1ull) : ((st1 >> (iB - 64)) & 1ull);
            bool cvB = (iB < 64) ? ((cv0 >> iB) & 1ull) : ((cv1 >> (iB - 64)) & 1ull);
            bool accA = valA && !((((st0 & sA0) | (st1 & sA1)) != 0ull) || cvA);
            bool accB = valB && !((((st0 & sB0) | (st1 & sB1)) != 0ull) || cvB);
            bool schgA = accA && (upA || !stA);
            bool schgB = accB && (upB || !stB);

            unsigned long long bInv =
                (unsigned long long)__ballot_sync(FULLMASK, !valA) |
                ((unsigned long long)__ballot_sync(FULLMASK, !valB) << 32);
            unsigned long long bS =
                (unsigned long long)__ballot_sync(FULLMASK, schgA) |
                ((unsigned long long)__ballot_sync(FULLMASK, schgB) << 32);
            int fI = bInv ? (__ffsll((long long)bInv) - 1) : 64;
            if (fI < 64) bS &= (fI ? ((1ull << fI) - 1ull) : 0ull);
            int fS = bS ? (__ffsll((long long)bS) - 1) : 64;
            int lim = fS < fI ? fS : fI;

            if (accA && lane < lim) rB[idxA] = (float)avA;
            if (accB && 32 + lane < lim) rB[idxB] = (float)avB;

            if (fS < fI && fS < 64) {
                int sl = fS & 31;
                bool second = fS >= 32;
                if (lane == sl) {
                    int i = second ? iB : iA;
                    bool up = second ? upB : upA;
                    unsigned long long p0 = second ? sB0 : sA0;
                    unsigned long long p1 = second ? sB1 : sA1;
                    rB[second ? idxB : idxA] = (float)(second ? avB : avA);
                    if (i < 64) st0 |= (1ull << i); else st1 |= (1ull << (i - 64));
                    if (up) { cv0 |= p0; cv1 |= p1; }
                }
                st0 = __shfl_sync(FULLMASK, st0, sl);
                st1 = __shfl_sync(FULLMASK, st1, sl);
                cv0 = __shfl_sync(FULLMASK, cv0, sl);
                cv1 = __shfl_sync(FULLMASK, cv1, sl);
                t += fS + 1;
            } else if (fI < 64) {
                break;
            } else {
                t += 64;
            }
        }
    }
}

// ============================================================================
extern "C" void kernel_launch(void* const* d_in, const int* in_sizes, int n_in,
                              void* d_out, int out_size) {
    (void)in_sizes; (void)n_in;
    const float* bert = (const float*)d_in[0];
    const int*   tagseq = (const int*)d_in[1];
    const float* wS = (const float*)d_in[2];
    const float* bS = (const float*)d_in[3];
    const float* wE = (const float*)d_in[4];
    const float* bE = (const float*)d_in[5];
    const float* Wb = (const float*)d_in[6];
    float* out = (float*)d_out;

    pad_w_kernel<<<(OO * LDX * LDX + 255) / 256, 256>>>(Wb);
    proj_kernel<<<dim3(96, 2), 160>>>(bert, wS, bS, wE, bE);
    biaff_left<<<dim3(48, 9), 160>>>();
    biaff_right<<<dim3(9, 48), 128>>>();

    bool scoreInOut = (out_size >= SCORE_ELEMS);
    if (scoreInOut)
        transpose_kernel<<<1536, 256>>>(out);

    float* resPtr = nullptr;
    if (out_size >= SCORE_ELEMS + RESULT_ELEMS) resPtr = out + SCORE_ELEMS;
    else if (!scoreInOut && out_size >= RESULT_ELEMS) resPtr = out;

    if (resPtr) {
        cudaFuncSetAttribute(decode_kernel,
                             cudaFuncAttributeMaxDynamicSharedMemorySize, DEC_SMEM);
        decode_kernel<<<48, 1024, DEC_SMEM>>>(tagseq, resPtr);
    }
}